// round 1
// baseline (speedup 1.0000x reference)
#include <cuda_runtime.h>
#include <cuda_bf16.h>
#include <cstdint>

// Problem dims (fixed by the dataset)
#define B   64
#define D   3072
#define NA  4
#define A   2048
#define NN  (NA * A)        // 8192
#define KC  256             // K-chunk held in smem per iteration
#define THRESHOLD 0.02f

// Scratch (static device globals — no allocation allowed)
__device__ float g_gate[NA];
__device__ float g_znew[B * NN];   // 2 MB

// ---------- f32x2 helpers ----------
__device__ __forceinline__ unsigned long long pack2(float lo, float hi) {
    unsigned long long d;
    asm("mov.b64 %0, {%1, %2};" : "=l"(d) : "f"(lo), "f"(hi));
    return d;
}
__device__ __forceinline__ unsigned long long fma2(unsigned long long a,
                                                   unsigned long long b,
                                                   unsigned long long c) {
    unsigned long long d;
    asm("fma.rn.f32x2 %0, %1, %2, %3;" : "=l"(d) : "l"(a), "l"(b), "l"(c));
    return d;
}
__device__ __forceinline__ void unpack2(unsigned long long v, float& lo, float& hi) {
    asm("mov.b64 {%0, %1}, %2;" : "=f"(lo), "=f"(hi) : "l"(v));
}

// ---------- Kernel 1: gate per area ----------
__global__ void gate_kernel(const float* __restrict__ Z) {
    int i = blockIdx.x;            // area
    int t = threadIdx.x;
    float s = 0.f;
    // 64 * 2048 = 131072 elements per area
    for (int idx = t; idx < B * A; idx += 256) {
        int b = idx >> 11;
        int a = idx & (A - 1);
        s += fabsf(Z[(size_t)b * NN + (size_t)i * A + a]);
    }
    __shared__ float red[256];
    red[t] = s;
    __syncthreads();
    for (int st = 128; st > 0; st >>= 1) {
        if (t < st) red[t] += red[t + st];
        __syncthreads();
    }
    if (t == 0)
        g_gate[i] = (red[0] * (1.0f / (float)(B * A)) > THRESHOLD) ? 1.0f : 0.0f;
}

// ---------- Kernel 2: fused einsum + stim + epilogue ----------
// Grid: 128 blocks x 256 threads. Each block owns 64 output columns.
// Thread t: column n = blk*64 + (t & 63), batch-group g = t >> 6 (16 batches).
// Accumulators: 16 x f32x2 (even-k / odd-k partial sums per batch).
__global__ __launch_bounds__(256, 1)
void main_kernel(const float* __restrict__ x,
                 const float* __restrict__ Z,
                 const float* __restrict__ Fstate,
                 const float* __restrict__ rw,       // receptors_w [N, D]
                 const float* __restrict__ rb,       // receptors_b [N]
                 const float* __restrict__ W,        // [NA,NA,A,A]
                 const float* __restrict__ Wmask,    // [NA,NA,A,A]
                 const float* __restrict__ bias_diag)// [NA,A]
{
    __shared__ __align__(16) float zs[B * KC];   // [b][k] layout, 64 KB

    const int t = threadIdx.x;
    const int n = blockIdx.x * 64 + (t & 63);
    const int g = t >> 6;                 // 0..3
    const int o = n >> 11;                // n / A
    const int u = n & (A - 1);            // n % A

    float gates[NA];
#pragma unroll
    for (int i = 0; i < NA; i++) gates[i] = g_gate[i];

    unsigned long long acc[16];
#pragma unroll
    for (int bi = 0; bi < 16; bi++) acc[bi] = 0ULL;

    const float* zrow_base = zs + (size_t)(g * 16) * KC;

    // ================= einsum over K = 8192 =================
    for (int k0 = 0; k0 < NN; k0 += KC) {
        const int i = k0 >> 11;           // area of this whole chunk
        const float gk = gates[i];
        // cooperative load of Z[:, k0:k0+KC] (gated) into zs[b][j]
#pragma unroll
        for (int v = 0; v < 16; v++) {
            int f = t + 256 * v;          // float4 index, 4096 total
            int p = f << 2;
            int b = p >> 8;               // p / KC
            int j = p & (KC - 1);
            float4 zv = *reinterpret_cast<const float4*>(Z + (size_t)b * NN + k0 + j);
            zv.x *= gk; zv.y *= gk; zv.z *= gk; zv.w *= gk;
            *reinterpret_cast<float4*>(zs + (size_t)b * KC + j) = zv;
        }
        __syncthreads();

        const size_t woff = ((size_t)o << 24) + ((size_t)i << 22) +
                            ((size_t)u << 11) + (size_t)(k0 & (A - 1));
        const float* wrow = W + woff;
        const float* mrow = Wmask + woff;

#pragma unroll 4
        for (int k = 0; k < KC; k += 4) {
            float4 wv = *reinterpret_cast<const float4*>(wrow + k);
            float4 mv = *reinterpret_cast<const float4*>(mrow + k);
            unsigned long long wp0 = pack2(wv.x * __saturatef(mv.x),
                                           wv.y * __saturatef(mv.y));
            unsigned long long wp1 = pack2(wv.z * __saturatef(mv.z),
                                           wv.w * __saturatef(mv.w));
#pragma unroll
            for (int bi = 0; bi < 16; bi++) {
                ulonglong2 av = *reinterpret_cast<const ulonglong2*>(
                    zrow_base + (size_t)bi * KC + k);
                acc[bi] = fma2(wp0, av.x, acc[bi]);
                acc[bi] = fma2(wp1, av.y, acc[bi]);
            }
        }
        __syncthreads();
    }

    // ================= stim over K = 3072 =================
    for (int d0 = 0; d0 < D; d0 += KC) {
#pragma unroll
        for (int v = 0; v < 16; v++) {
            int f = t + 256 * v;
            int p = f << 2;
            int b = p >> 8;
            int j = p & (KC - 1);
            float4 xv = *reinterpret_cast<const float4*>(x + (size_t)b * D + d0 + j);
            *reinterpret_cast<float4*>(zs + (size_t)b * KC + j) = xv;
        }
        __syncthreads();

        const float* wrow = rw + (size_t)n * D + d0;
#pragma unroll 4
        for (int k = 0; k < KC; k += 4) {
            float4 wv = *reinterpret_cast<const float4*>(wrow + k);
            unsigned long long wp0 = pack2(wv.x, wv.y);
            unsigned long long wp1 = pack2(wv.z, wv.w);
#pragma unroll
            for (int bi = 0; bi < 16; bi++) {
                ulonglong2 av = *reinterpret_cast<const ulonglong2*>(
                    zrow_base + (size_t)bi * KC + k);
                acc[bi] = fma2(wp0, av.x, acc[bi]);
                acc[bi] = fma2(wp1, av.y, acc[bi]);
            }
        }
        __syncthreads();
    }

    // ================= epilogue =================
    const float rbn = rb[n];
    const float bterm = bias_diag[n] * gates[o];   // bias_diag flat index == n
#pragma unroll
    for (int bi = 0; bi < 16; bi++) {
        int b = g * 16 + bi;
        float lo, hi;
        unpack2(acc[bi], lo, hi);
        size_t idx = (size_t)b * NN + n;
        float zp = lo + hi + rbn + bterm
                 - 0.8f * Fstate[idx] - 0.4f * Z[idx];
        g_znew[idx] = tanhf(zp);
    }
}

// ---------- Kernel 3: output projection (N=11) ----------
__global__ void out_kernel(const float* __restrict__ out_w,   // [11, N]
                           const float* __restrict__ out_b,   // [11]
                           float* __restrict__ out)           // [B, 11]
{
    int b = blockIdx.x;
    int t = threadIdx.x;
    float p[11];
#pragma unroll
    for (int j = 0; j < 11; j++) p[j] = 0.f;

    for (int n = t; n < NN; n += 256) {
        float z = g_znew[(size_t)b * NN + n];
#pragma unroll
        for (int j = 0; j < 11; j++) p[j] += z * out_w[(size_t)j * NN + n];
    }

    __shared__ float red[11 * 256];
#pragma unroll
    for (int j = 0; j < 11; j++) red[j * 256 + t] = p[j];
    __syncthreads();
    for (int st = 128; st > 0; st >>= 1) {
        if (t < st) {
#pragma unroll
            for (int j = 0; j < 11; j++) red[j * 256 + t] += red[j * 256 + t + st];
        }
        __syncthreads();
    }
    if (t < 11) {
        float r = red[t * 256] + out_b[t];
        out[(size_t)b * 11 + t] = (t < 10) ? r : 1.0f / (1.0f + expf(-r));
    }
}

// ---------- launch ----------
extern "C" void kernel_launch(void* const* d_in, const int* in_sizes, int n_in,
                              void* d_out, int out_size) {
    const float* x        = (const float*)d_in[0];   // (64, 3072)
    const float* Z        = (const float*)d_in[1];   // (64, 4, 2048)
    const float* Fstate   = (const float*)d_in[2];   // (64, 4, 2048)
    const float* rw       = (const float*)d_in[3];   // (8192, 3072)
    const float* rb       = (const float*)d_in[4];   // (8192,)
    const float* W        = (const float*)d_in[5];   // (4,4,2048,2048)
    const float* Wmask    = (const float*)d_in[6];   // (4,4,2048,2048)
    const float* bias_d   = (const float*)d_in[7];   // (4,2048)
    const float* out_w    = (const float*)d_in[8];   // (11, 8192)
    const float* out_b    = (const float*)d_in[9];   // (11,)
    // d_in[10] = area_idx (arange, identity scatter) — unused
    float* out = (float*)d_out;                      // (64, 11)

    gate_kernel<<<NA, 256>>>(Z);
    main_kernel<<<NN / 64, 256>>>(x, Z, Fstate, rw, rb, W, Wmask, bias_d);
    out_kernel<<<B, 256>>>(out_w, out_b, out);
}